// round 13
// baseline (speedup 1.0000x reference)
#include <cuda_runtime.h>
#include <cuda_bf16.h>
#include <mma.h>
#include <cstdint>
#include <cstddef>

// ============================================================================
// y[M,N] = bf16( bf16( bf15(x)[M,K] @ W[N,K]^T ) + bias[N] ) -> stored FP32
//   M=32768, N=4096, K=1024
// R11: 1600us (tensor ~56%, smem co-binding, 2 barriers/chunk).
// R12: 3-stage cp.async pipeline with ONE syncthreads per chunk (safe with
//      >=3 stages), same 256x128 CTA / 64x64 warp tiles / 144B rows.
// ============================================================================

using namespace nvcuda;

static constexpr int MT = 32768;
static constexpr int NT = 4096;
static constexpr int KT = 1024;
static constexpr int TM = 256;
static constexpr int TN = 128;
static constexpr int CK = 64;                 // k-chunk
static constexpr int NCHUNK = KT / CK;        // 16
static constexpr int THREADS = 256;           // 8 warps: 4(M) x 2(N), warp 64x64
static constexpr int NSTAGE = 3;

static constexpr uint32_t ROWB  = 144;        // smem row stride bytes (36 words)
static constexpr int      LDSMW = 72;         // row stride in bf16 elems
static constexpr uint32_t OFF_A = 0;                      // 256*144 = 36864
static constexpr uint32_t OFF_H = 36864;                  // 128*144 = 18432
static constexpr uint32_t OFF_L = 55296;                  // 128*144 = 18432
static constexpr uint32_t STAGE = 73728;
static constexpr uint32_t OFF_BIAS = NSTAGE * STAGE;      // 221184 (512B)
static constexpr uint32_t SMEM_BYTES = OFF_BIAS + 512;    // 221696

__device__ __nv_bfloat16 g_A [33554432];  // [M,K] bf15-as-bf16
__device__ __nv_bfloat16 g_Wh[ 4194304];  // [N,K] bf16(W)
__device__ __nv_bfloat16 g_Wl[ 4194304];  // [N,K] bf16(W - bf16(W))

#define DEVFN __device__ __forceinline__
DEVFN uint32_t smem_u32(const void* p) {
    uint32_t a;
    asm("{ .reg .u64 t; cvta.to.shared.u64 t, %1; cvt.u32.u64 %0, t; }" : "=r"(a) : "l"(p));
    return a;
}
DEVFN void cp_async16(uint32_t dst, const void* src) {
    asm volatile("cp.async.cg.shared.global [%0], [%1], 16;" :: "r"(dst), "l"(src));
}
#define CP_COMMIT() asm volatile("cp.async.commit_group;" ::: "memory")
#define CP_WAIT(n)  asm volatile("cp.async.wait_group %0;" :: "n"(n) : "memory")

// ---------------------------------------------------------------------------
// Kernel 1: x fp32 -> bf15 (exact in bf16: truncate to 6 mantissa bits)
// ---------------------------------------------------------------------------
__global__ void __launch_bounds__(256) conv_x_kernel(const float4* __restrict__ x) {
    int i = blockIdx.x * 256 + threadIdx.x;   // one float4 per thread, exact cover
    float4 v = x[i];
    uint32_t a = __float_as_uint(v.x), b = __float_as_uint(v.y);
    uint32_t c = __float_as_uint(v.z), d = __float_as_uint(v.w);
    uint2 o;
    o.x = ((a >> 16) & 0xFFFEu) | (b & 0xFFFE0000u);
    o.y = ((c >> 16) & 0xFFFEu) | (d & 0xFFFE0000u);
    reinterpret_cast<uint2*>(g_A)[i] = o;
}

// ---------------------------------------------------------------------------
// Kernel 2: W fp32 -> bf16 hi + bf16 residual
// ---------------------------------------------------------------------------
__global__ void __launch_bounds__(256) split_w_kernel(const float2* __restrict__ w) {
    int i = blockIdx.x * 256 + threadIdx.x;   // one float2 per thread, exact cover
    float2 v = w[i];
    __nv_bfloat16 h0 = __float2bfloat16(v.x);
    __nv_bfloat16 h1 = __float2bfloat16(v.y);
    __nv_bfloat16 l0 = __float2bfloat16(v.x - __bfloat162float(h0));
    __nv_bfloat16 l1 = __float2bfloat16(v.y - __bfloat162float(h1));
    uint32_t ph = (uint32_t)__bfloat16_as_ushort(h0) | ((uint32_t)__bfloat16_as_ushort(h1) << 16);
    uint32_t pl = (uint32_t)__bfloat16_as_ushort(l0) | ((uint32_t)__bfloat16_as_ushort(l1) << 16);
    reinterpret_cast<uint32_t*>(g_Wh)[i] = ph;
    reinterpret_cast<uint32_t*>(g_Wl)[i] = pl;
}

// ---------------------------------------------------------------------------
// Kernel 3: GEMM — 3-stage pipeline, one barrier per chunk
// ---------------------------------------------------------------------------
__global__ void __launch_bounds__(THREADS, 1)
gemm_kernel(const float* __restrict__ bias, float* __restrict__ out) {
    extern __shared__ __align__(16) char smem[];
    const uint32_t sb = smem_u32(smem);

    const int tid    = threadIdx.x;
    const int wid    = tid >> 5;
    const int lane   = tid & 31;
    const int warp_m = wid >> 1;   // 0..3 (64 rows)
    const int warp_n = wid & 1;    // 0..1 (64 cols)

    // n-fastest order: A band shared by 32 consecutive CTAs; W L2-resident
    const int bid = blockIdx.x;
    const int m0  = (bid >> 5) * TM;   // 128 m-tiles
    const int n0  = (bid & 31) * TN;   // 32 n-tiles

    if (tid < TN)
        reinterpret_cast<float*>(smem + OFF_BIAS)[tid] = bias[n0 + tid];

    const __nv_bfloat16* Ab = g_A  + (size_t)m0 * KT;
    const __nv_bfloat16* Hb = g_Wh + (size_t)n0 * KT;
    const __nv_bfloat16* Lb = g_Wl + (size_t)n0 * KT;

    auto load_stage = [&](int ks, int s) {
        const uint32_t base = sb + (uint32_t)s * STAGE;
        const __nv_bfloat16* ak = Ab + ks * CK;
        const __nv_bfloat16* hk = Hb + ks * CK;
        const __nv_bfloat16* lk = Lb + ks * CK;
        #pragma unroll
        for (int i = tid; i < 2048; i += THREADS) {       // A: 256 rows x 8x16B
            int r = i >> 3, c = i & 7;
            cp_async16(base + OFF_A + (uint32_t)r * ROWB + c * 16,
                       ak + (size_t)r * KT + c * 8);
        }
        #pragma unroll
        for (int i = tid; i < 1024; i += THREADS) {       // Wh/Wl: 128 rows x 8x16B
            int r = i >> 3, c = i & 7;
            uint32_t doff = (uint32_t)r * ROWB + c * 16;
            cp_async16(base + OFF_H + doff, hk + (size_t)r * KT + c * 8);
            cp_async16(base + OFF_L + doff, lk + (size_t)r * KT + c * 8);
        }
    };

    wmma::fragment<wmma::accumulator, 16, 16, 16, float> acc[4][4];
    #pragma unroll
    for (int mi = 0; mi < 4; mi++)
        #pragma unroll
        for (int nj = 0; nj < 4; nj++)
            wmma::fill_fragment(acc[mi][nj], 0.0f);

    load_stage(0, 0); CP_COMMIT();
    load_stage(1, 1); CP_COMMIT();

    #pragma unroll 1
    for (int ks = 0; ks < NCHUNK; ks++) {
        if (ks + 1 < NCHUNK) { CP_WAIT(1); } else { CP_WAIT(0); }
        __syncthreads();   // all warps done with stage (ks-1); stage ks ready
        if (ks + 2 < NCHUNK) {
            load_stage(ks + 2, (ks + 2) % NSTAGE);        // buffer (ks-1)%3, now free
            CP_COMMIT();
        }

        const char* stg = smem + (uint32_t)(ks % NSTAGE) * STAGE;
        const __nv_bfloat16* sA = reinterpret_cast<const __nv_bfloat16*>(stg + OFF_A);
        const __nv_bfloat16* sH = reinterpret_cast<const __nv_bfloat16*>(stg + OFF_H);
        const __nv_bfloat16* sL = reinterpret_cast<const __nv_bfloat16*>(stg + OFF_L);

        #pragma unroll
        for (int kk = 0; kk < 4; kk++) {                  // four k16 steps
            wmma::fragment<wmma::matrix_a, 16, 16, 16, __nv_bfloat16,
                           wmma::row_major> af[4];
            #pragma unroll
            for (int mi = 0; mi < 4; mi++)
                wmma::load_matrix_sync(
                    af[mi], &sA[(warp_m * 64 + mi * 16) * LDSMW + kk * 16], LDSMW);
            #pragma unroll
            for (int nj = 0; nj < 4; nj++) {
                wmma::fragment<wmma::matrix_b, 16, 16, 16, __nv_bfloat16,
                               wmma::col_major> bh, bl;
                const int nrow = (warp_n * 64 + nj * 16) * LDSMW + kk * 16;
                wmma::load_matrix_sync(bh, &sH[nrow], LDSMW);
                wmma::load_matrix_sync(bl, &sL[nrow], LDSMW);
                #pragma unroll
                for (int mi = 0; mi < 4; mi++) {
                    wmma::mma_sync(acc[mi][nj], af[mi], bh, acc[mi][nj]);
                    wmma::mma_sync(acc[mi][nj], af[mi], bl, acc[mi][nj]);
                }
            }
        }
    }

    // ---- epilogue: g=bf16(acc); y=bf16(fp32(g)+bias); store fp32(y) ---------
    __syncthreads();   // all reads of the last stage done; reuse stage 0 region
    float* cs = reinterpret_cast<float*>(smem) + wid * 256;
    const float* bias_sm = reinterpret_cast<const float*>(smem + OFF_BIAS);
    const int r0 = lane >> 3;          // 0..3
    const int wd = lane & 7;           // col-pair within 16
    #pragma unroll
    for (int mi = 0; mi < 4; mi++) {
        #pragma unroll
        for (int nj = 0; nj < 4; nj++) {
            wmma::store_matrix_sync(cs, acc[mi][nj], 16, wmma::mem_row_major);
            __syncwarp();
            const int colb = warp_n * 64 + nj * 16 + 2 * wd;    // within CTA tile
            const float bb0 = bias_sm[colb];
            const float bb1 = bias_sm[colb + 1];
            #pragma unroll
            for (int t = 0; t < 4; t++) {
                const int r = r0 + 4 * t;                       // 0..15
                float c0 = cs[r * 16 + 2 * wd];
                float c1 = cs[r * 16 + 2 * wd + 1];
                __nv_bfloat16 g0 = __float2bfloat16(c0);        // first rounding
                __nv_bfloat16 g1 = __float2bfloat16(c1);
                __nv_bfloat16 y0 = __float2bfloat16(__bfloat162float(g0) + bb0);
                __nv_bfloat16 y1 = __float2bfloat16(__bfloat162float(g1) + bb1);
                const size_t grow = (size_t)(m0 + warp_m * 64 + mi * 16 + r);
                float2 o;
                o.x = __bfloat162float(y0);
                o.y = __bfloat162float(y1);
                *reinterpret_cast<float2*>(out + grow * NT + n0 + colb) = o;
            }
            __syncwarp();
        }
    }
}

// ---------------------------------------------------------------------------
extern "C" void kernel_launch(void* const* d_in, const int* in_sizes, int n_in,
                              void* d_out, int out_size) {
    // Resolve inputs BY SIZE (order-proof): x 33554432, weight 4194304, bias 4096
    const float* x    = nullptr;
    const float* w    = nullptr;
    const float* bias = nullptr;
    for (int i = 0; i < n_in; i++) {
        if (in_sizes[i] == 33554432)      x    = (const float*)d_in[i];
        else if (in_sizes[i] == 4194304)  w    = (const float*)d_in[i];
        else if (in_sizes[i] == 4096)     bias = (const float*)d_in[i];
    }
    if (!x)    x    = (const float*)d_in[0];
    if (!w)    w    = (const float*)d_in[1];
    if (!bias) bias = (const float*)d_in[2];

    float* out = (float*)d_out;   // __output__ dtype: float32

    static bool attr = false;
    if (!attr) {
        cudaFuncSetAttribute(gemm_kernel, cudaFuncAttributeMaxDynamicSharedMemorySize,
                             SMEM_BYTES);
        attr = true;
    }

    conv_x_kernel<<<(MT * KT / 4) / 256, 256>>>(reinterpret_cast<const float4*>(x));
    split_w_kernel<<<(NT * KT / 2) / 256, 256>>>(reinterpret_cast<const float2*>(w));
    gemm_kernel<<<(MT / TM) * (NT / TN), THREADS, SMEM_BYTES>>>(bias, out);
}

// round 14
// speedup vs baseline: 1.0007x; 1.0007x over previous
#include <cuda_runtime.h>
#include <cuda_bf16.h>
#include <mma.h>
#include <cstdint>
#include <cstddef>

// ============================================================================
// y[M,N] = bf16( bf16( bf15(x)[M,K] @ W[N,K]^T ) + bias[N] ) -> stored FP32
//   M=32768, N=4096, K=1024
// R11: 1600us (tensor ~56%, smem co-binding, 2 barriers/chunk).
// R12: 3-stage cp.async pipeline with ONE syncthreads per chunk (safe with
//      >=3 stages), same 256x128 CTA / 64x64 warp tiles / 144B rows.
// ============================================================================

using namespace nvcuda;

static constexpr int MT = 32768;
static constexpr int NT = 4096;
static constexpr int KT = 1024;
static constexpr int TM = 256;
static constexpr int TN = 128;
static constexpr int CK = 64;                 // k-chunk
static constexpr int NCHUNK = KT / CK;        // 16
static constexpr int THREADS = 256;           // 8 warps: 4(M) x 2(N), warp 64x64
static constexpr int NSTAGE = 3;

static constexpr uint32_t ROWB  = 144;        // smem row stride bytes (36 words)
static constexpr int      LDSMW = 72;         // row stride in bf16 elems
static constexpr uint32_t OFF_A = 0;                      // 256*144 = 36864
static constexpr uint32_t OFF_H = 36864;                  // 128*144 = 18432
static constexpr uint32_t OFF_L = 55296;                  // 128*144 = 18432
static constexpr uint32_t STAGE = 73728;
static constexpr uint32_t OFF_BIAS = NSTAGE * STAGE;      // 221184 (512B)
static constexpr uint32_t SMEM_BYTES = OFF_BIAS + 512;    // 221696

__device__ __nv_bfloat16 g_A [33554432];  // [M,K] bf15-as-bf16
__device__ __nv_bfloat16 g_Wh[ 4194304];  // [N,K] bf16(W)
__device__ __nv_bfloat16 g_Wl[ 4194304];  // [N,K] bf16(W - bf16(W))

#define DEVFN __device__ __forceinline__
DEVFN uint32_t smem_u32(const void* p) {
    uint32_t a;
    asm("{ .reg .u64 t; cvta.to.shared.u64 t, %1; cvt.u32.u64 %0, t; }" : "=r"(a) : "l"(p));
    return a;
}
DEVFN void cp_async16(uint32_t dst, const void* src) {
    asm volatile("cp.async.cg.shared.global [%0], [%1], 16;" :: "r"(dst), "l"(src));
}
#define CP_COMMIT() asm volatile("cp.async.commit_group;" ::: "memory")
#define CP_WAIT(n)  asm volatile("cp.async.wait_group %0;" :: "n"(n) : "memory")

// ---------------------------------------------------------------------------
// Kernel 1: x fp32 -> bf15 (exact in bf16: truncate to 6 mantissa bits)
// ---------------------------------------------------------------------------
__global__ void __launch_bounds__(256) conv_x_kernel(const float4* __restrict__ x) {
    int i = blockIdx.x * 256 + threadIdx.x;   // one float4 per thread, exact cover
    float4 v = x[i];
    uint32_t a = __float_as_uint(v.x), b = __float_as_uint(v.y);
    uint32_t c = __float_as_uint(v.z), d = __float_as_uint(v.w);
    uint2 o;
    o.x = ((a >> 16) & 0xFFFEu) | (b & 0xFFFE0000u);
    o.y = ((c >> 16) & 0xFFFEu) | (d & 0xFFFE0000u);
    reinterpret_cast<uint2*>(g_A)[i] = o;
}

// ---------------------------------------------------------------------------
// Kernel 2: W fp32 -> bf16 hi + bf16 residual
// ---------------------------------------------------------------------------
__global__ void __launch_bounds__(256) split_w_kernel(const float2* __restrict__ w) {
    int i = blockIdx.x * 256 + threadIdx.x;   // one float2 per thread, exact cover
    float2 v = w[i];
    __nv_bfloat16 h0 = __float2bfloat16(v.x);
    __nv_bfloat16 h1 = __float2bfloat16(v.y);
    __nv_bfloat16 l0 = __float2bfloat16(v.x - __bfloat162float(h0));
    __nv_bfloat16 l1 = __float2bfloat16(v.y - __bfloat162float(h1));
    uint32_t ph = (uint32_t)__bfloat16_as_ushort(h0) | ((uint32_t)__bfloat16_as_ushort(h1) << 16);
    uint32_t pl = (uint32_t)__bfloat16_as_ushort(l0) | ((uint32_t)__bfloat16_as_ushort(l1) << 16);
    reinterpret_cast<uint32_t*>(g_Wh)[i] = ph;
    reinterpret_cast<uint32_t*>(g_Wl)[i] = pl;
}

// ---------------------------------------------------------------------------
// Kernel 3: GEMM — 3-stage pipeline, one barrier per chunk
// ---------------------------------------------------------------------------
__global__ void __launch_bounds__(THREADS, 1)
gemm_kernel(const float* __restrict__ bias, float* __restrict__ out) {
    extern __shared__ __align__(16) char smem[];
    const uint32_t sb = smem_u32(smem);

    const int tid    = threadIdx.x;
    const int wid    = tid >> 5;
    const int lane   = tid & 31;
    const int warp_m = wid >> 1;   // 0..3 (64 rows)
    const int warp_n = wid & 1;    // 0..1 (64 cols)

    // n-fastest order: A band shared by 32 consecutive CTAs; W L2-resident
    const int bid = blockIdx.x;
    const int m0  = (bid >> 5) * TM;   // 128 m-tiles
    const int n0  = (bid & 31) * TN;   // 32 n-tiles

    if (tid < TN)
        reinterpret_cast<float*>(smem + OFF_BIAS)[tid] = bias[n0 + tid];

    const __nv_bfloat16* Ab = g_A  + (size_t)m0 * KT;
    const __nv_bfloat16* Hb = g_Wh + (size_t)n0 * KT;
    const __nv_bfloat16* Lb = g_Wl + (size_t)n0 * KT;

    auto load_stage = [&](int ks, int s) {
        const uint32_t base = sb + (uint32_t)s * STAGE;
        const __nv_bfloat16* ak = Ab + ks * CK;
        const __nv_bfloat16* hk = Hb + ks * CK;
        const __nv_bfloat16* lk = Lb + ks * CK;
        #pragma unroll
        for (int i = tid; i < 2048; i += THREADS) {       // A: 256 rows x 8x16B
            int r = i >> 3, c = i & 7;
            cp_async16(base + OFF_A + (uint32_t)r * ROWB + c * 16,
                       ak + (size_t)r * KT + c * 8);
        }
        #pragma unroll
        for (int i = tid; i < 1024; i += THREADS) {       // Wh/Wl: 128 rows x 8x16B
            int r = i >> 3, c = i & 7;
            uint32_t doff = (uint32_t)r * ROWB + c * 16;
            cp_async16(base + OFF_H + doff, hk + (size_t)r * KT + c * 8);
            cp_async16(base + OFF_L + doff, lk + (size_t)r * KT + c * 8);
        }
    };

    wmma::fragment<wmma::accumulator, 16, 16, 16, float> acc[4][4];
    #pragma unroll
    for (int mi = 0; mi < 4; mi++)
        #pragma unroll
        for (int nj = 0; nj < 4; nj++)
            wmma::fill_fragment(acc[mi][nj], 0.0f);

    load_stage(0, 0); CP_COMMIT();
    load_stage(1, 1); CP_COMMIT();

    #pragma unroll 1
    for (int ks = 0; ks < NCHUNK; ks++) {
        if (ks + 1 < NCHUNK) { CP_WAIT(1); } else { CP_WAIT(0); }
        __syncthreads();   // all warps done with stage (ks-1); stage ks ready
        if (ks + 2 < NCHUNK) {
            load_stage(ks + 2, (ks + 2) % NSTAGE);        // buffer (ks-1)%3, now free
            CP_COMMIT();
        }

        const char* stg = smem + (uint32_t)(ks % NSTAGE) * STAGE;
        const __nv_bfloat16* sA = reinterpret_cast<const __nv_bfloat16*>(stg + OFF_A);
        const __nv_bfloat16* sH = reinterpret_cast<const __nv_bfloat16*>(stg + OFF_H);
        const __nv_bfloat16* sL = reinterpret_cast<const __nv_bfloat16*>(stg + OFF_L);

        #pragma unroll
        for (int kk = 0; kk < 4; kk++) {                  // four k16 steps
            wmma::fragment<wmma::matrix_a, 16, 16, 16, __nv_bfloat16,
                           wmma::row_major> af[4];
            #pragma unroll
            for (int mi = 0; mi < 4; mi++)
                wmma::load_matrix_sync(
                    af[mi], &sA[(warp_m * 64 + mi * 16) * LDSMW + kk * 16], LDSMW);
            #pragma unroll
            for (int nj = 0; nj < 4; nj++) {
                wmma::fragment<wmma::matrix_b, 16, 16, 16, __nv_bfloat16,
                               wmma::col_major> bh, bl;
                const int nrow = (warp_n * 64 + nj * 16) * LDSMW + kk * 16;
                wmma::load_matrix_sync(bh, &sH[nrow], LDSMW);
                wmma::load_matrix_sync(bl, &sL[nrow], LDSMW);
                #pragma unroll
                for (int mi = 0; mi < 4; mi++) {
                    wmma::mma_sync(acc[mi][nj], af[mi], bh, acc[mi][nj]);
                    wmma::mma_sync(acc[mi][nj], af[mi], bl, acc[mi][nj]);
                }
            }
        }
    }

    // ---- epilogue: g=bf16(acc); y=bf16(fp32(g)+bias); store fp32(y) ---------
    __syncthreads();   // all reads of the last stage done; reuse stage 0 region
    float* cs = reinterpret_cast<float*>(smem) + wid * 256;
    const float* bias_sm = reinterpret_cast<const float*>(smem + OFF_BIAS);
    const int r0 = lane >> 3;          // 0..3
    const int wd = lane & 7;           // col-pair within 16
    #pragma unroll
    for (int mi = 0; mi < 4; mi++) {
        #pragma unroll
        for (int nj = 0; nj < 4; nj++) {
            wmma::store_matrix_sync(cs, acc[mi][nj], 16, wmma::mem_row_major);
            __syncwarp();
            const int colb = warp_n * 64 + nj * 16 + 2 * wd;    // within CTA tile
            const float bb0 = bias_sm[colb];
            const float bb1 = bias_sm[colb + 1];
            #pragma unroll
            for (int t = 0; t < 4; t++) {
                const int r = r0 + 4 * t;                       // 0..15
                float c0 = cs[r * 16 + 2 * wd];
                float c1 = cs[r * 16 + 2 * wd + 1];
                __nv_bfloat16 g0 = __float2bfloat16(c0);        // first rounding
                __nv_bfloat16 g1 = __float2bfloat16(c1);
                __nv_bfloat16 y0 = __float2bfloat16(__bfloat162float(g0) + bb0);
                __nv_bfloat16 y1 = __float2bfloat16(__bfloat162float(g1) + bb1);
                const size_t grow = (size_t)(m0 + warp_m * 64 + mi * 16 + r);
                float2 o;
                o.x = __bfloat162float(y0);
                o.y = __bfloat162float(y1);
                *reinterpret_cast<float2*>(out + grow * NT + n0 + colb) = o;
            }
            __syncwarp();
        }
    }
}

// ---------------------------------------------------------------------------
extern "C" void kernel_launch(void* const* d_in, const int* in_sizes, int n_in,
                              void* d_out, int out_size) {
    // Resolve inputs BY SIZE (order-proof): x 33554432, weight 4194304, bias 4096
    const float* x    = nullptr;
    const float* w    = nullptr;
    const float* bias = nullptr;
    for (int i = 0; i < n_in; i++) {
        if (in_sizes[i] == 33554432)      x    = (const float*)d_in[i];
        else if (in_sizes[i] == 4194304)  w    = (const float*)d_in[i];
        else if (in_sizes[i] == 4096)     bias = (const float*)d_in[i];
    }
    if (!x)    x    = (const float*)d_in[0];
    if (!w)    w    = (const float*)d_in[1];
    if (!bias) bias = (const float*)d_in[2];

    float* out = (float*)d_out;   // __output__ dtype: float32

    static bool attr = false;
    if (!attr) {
        cudaFuncSetAttribute(gemm_kernel, cudaFuncAttributeMaxDynamicSharedMemorySize,
                             SMEM_BYTES);
        attr = true;
    }

    conv_x_kernel<<<(MT * KT / 4) / 256, 256>>>(reinterpret_cast<const float4*>(x));
    split_w_kernel<<<(NT * KT / 2) / 256, 256>>>(reinterpret_cast<const float2*>(w));
    gemm_kernel<<<(MT / TM) * (NT / TN), THREADS, SMEM_BYTES>>>(bias, out);
}